// round 17
// baseline (speedup 1.0000x reference)
#include <cuda_runtime.h>
#include <cuda_fp16.h>

// ---------------------------------------------------------------------------
// Fused BN -> sign(+-1) -> 3x3 conv -> bias -> ReLU, fp16 tensor-core
// implicit GEMM. Persistent CTAs, warp-specialized (R16 champion + R17):
//   warps 0-3: MMA (2 rows x 32 px x 32 co, dy-dedup k-loop) + pack accs to
//              fp16 scratch (cheap STS-only epilogue)
//   warps 4-7: build tile i+1 AND drain tile i-1 scratch -> bias+ReLU+STG,
//              both concurrent with MMA(i); single end-of-iter barrier.
// Double-buffered Q tiles and scratch. 2 CTAs/SM. Tile: 8r x 32px x 32co.
// ---------------------------------------------------------------------------

#define HW      65536
#define C_CH    32

#define QROWS   10           // 8 + 2 halo
#define QPX     34           // 32 + 2 halo
#define CIP     40           // ci stride (halfs) -> 80B px stride, ldsm-safe
#define QTILE   (QROWS * QPX * CIP)   // 13600 halfs
#define NWF4    (9 * 2 * 2 * 32)      // 1152 uint4 weight frag pairs
#define SCRW    36                    // scratch px stride (uints = half2)
#define SCRBUF  (8 * 16 * SCRW)       // 4608 uints per buffer (18432 B)

#define OFF_Q0  0
#define OFF_Q1  (QTILE * 2)
#define OFF_WF  (QTILE * 4)            // 54400
#define OFF_SI  (OFF_WF + NWF4 * 16)   // 72832 : sinvf float[32]
#define OFF_SS  (OFF_SI + 128)         // sshf  float[32]
#define OFF_SB  (OFF_SS + 128)         // sbias float[32]
#define OFF_SCR (OFF_SB + 128)         // 73344 : 2 x SCRBUF uints
#define SMEM_BYTES (OFF_SCR + 2 * SCRBUF * 4)   // 110208

#define NT      256
#define NCTA    296                    // 2 per SM x 148
#define NTILES  4096                   // 16 b x 32 y x 8 x (bx fastest)

__device__ __forceinline__ void ldsm_x4(unsigned &a0, unsigned &a1,
                                        unsigned &a2, unsigned &a3,
                                        unsigned addr) {
    asm volatile("ldmatrix.sync.aligned.m8n8.x4.shared.b16 {%0,%1,%2,%3}, [%4];"
                 : "=r"(a0), "=r"(a1), "=r"(a2), "=r"(a3) : "r"(addr));
}
__device__ __forceinline__ void mma16816(float &c0, float &c1, float &c2, float &c3,
                                         unsigned a0, unsigned a1, unsigned a2, unsigned a3,
                                         unsigned b0, unsigned b1) {
    asm volatile("mma.sync.aligned.m16n8k16.row.col.f32.f16.f16.f32 "
                 "{%0,%1,%2,%3},{%4,%5,%6,%7},{%8,%9},{%0,%1,%2,%3};"
                 : "+f"(c0), "+f"(c1), "+f"(c2), "+f"(c3)
                 : "r"(a0), "r"(a1), "r"(a2), "r"(a3), "r"(b0), "r"(b1));
}
__device__ __forceinline__ unsigned pk2(float f0, float iv0, float sh0,
                                        float f1, float iv1, float sh1, bool ok) {
    unsigned lo = ok ? (fmaf(f0, iv0, sh0) > 0.f ? 0x3C00u : 0xBC00u) : 0u;
    unsigned hi = ok ? (fmaf(f1, iv1, sh1) > 0.f ? 0x3C00u : 0xBC00u) : 0u;
    return lo | (hi << 16);
}
__device__ __forceinline__ void sts128(unsigned addr, uint4 v) {
    asm volatile("st.shared.v4.b32 [%0], {%1,%2,%3,%4};"
                 :: "r"(addr), "r"(v.x), "r"(v.y), "r"(v.z), "r"(v.w));
}
__device__ __forceinline__ void sts32(unsigned addr, unsigned v) {
    asm volatile("st.shared.b32 [%0], %1;" :: "r"(addr), "r"(v));
}
__device__ __forceinline__ unsigned lds32(unsigned addr) {
    unsigned v;
    asm volatile("ld.shared.b32 %0, [%1];" : "=r"(v) : "r"(addr));
    return v;
}
__device__ __forceinline__ unsigned h2bits(float a, float b) {
    __half2 h = __floats2half2_rn(a, b);
    return *reinterpret_cast<unsigned*>(&h);
}

// load one body row-group: 8 ci (group g) x 32 px for stored row r
__device__ __forceinline__ void ldrow(const float* __restrict__ xb,
                                      int by, int bx, int r, int g, int lane,
                                      float* F) {
    int gy = by + r - 1;
    bool ok = (unsigned)gy < 256u;
#pragma unroll
    for (int j = 0; j < 8; ++j) F[j] = 0.f;
    if (ok) {
        const float* p = xb + (size_t)(g * 8) * HW + (gy << 8) + bx + lane;
#pragma unroll
        for (int j = 0; j < 8; ++j) F[j] = __ldg(p + (size_t)j * HW);
    }
}
__device__ __forceinline__ void strow(unsigned qn, int by, int r, int g, int lane,
                                      const float* ivr, const float* shr,
                                      const float* F) {
    bool ok = (unsigned)(by + r - 1) < 256u;
    uint4 v;
    v.x = pk2(F[0], ivr[0], shr[0], F[1], ivr[1], shr[1], ok);
    v.y = pk2(F[2], ivr[2], shr[2], F[3], ivr[3], shr[3], ok);
    v.z = pk2(F[4], ivr[4], shr[4], F[5], ivr[5], shr[5], ok);
    v.w = pk2(F[6], ivr[6], shr[6], F[7], ivr[7], shr[7], ok);
    sts128(qn + (((r * QPX + lane + 1) * CIP + g * 8) << 1), v);
}
// halo item ht in [0,80): (r 0..9, side 0..1, oct 0..3), px 0 or 33
__device__ __forceinline__ void halo_item(unsigned qn, const float* __restrict__ xb,
                                          int by, int bx, int ht,
                                          const float* sinvf, const float* sshf) {
    if (ht >= 80) return;
    int r = ht >> 3, side = (ht >> 2) & 1, oct = ht & 3;
    int px = side ? 33 : 0;
    int gy = by + r - 1, gx = bx + px - 1;
    bool ok = ((unsigned)gy < 256u) & ((unsigned)gx < 256u);
    float f[8];
#pragma unroll
    for (int j = 0; j < 8; ++j) f[j] = 0.f;
    if (ok) {
        const float* p = xb + (size_t)(oct * 8) * HW + (gy << 8) + gx;
#pragma unroll
        for (int j = 0; j < 8; ++j) f[j] = __ldg(p + (size_t)j * HW);
    }
    const float* iv = sinvf + oct * 8;
    const float* sh = sshf + oct * 8;
    uint4 v;
    v.x = pk2(f[0], iv[0], sh[0], f[1], iv[1], sh[1], ok);
    v.y = pk2(f[2], iv[2], sh[2], f[3], iv[3], sh[3], ok);
    v.z = pk2(f[4], iv[4], sh[4], f[5], iv[5], sh[5], ok);
    v.w = pk2(f[6], iv[6], sh[6], f[7], iv[7], sh[7], ok);
    sts128(qn + (((r * QPX + px) * CIP + oct * 8) << 1), v);
}

// drain one scratch unit (r, cp) -> out, 32 px per lane
__device__ __forceinline__ void drain_unit(unsigned scrR, const float* sbias,
                                           float* ob, int pby, int pbx,
                                           int u, int lane) {
    int r = u >> 4, cp = u & 15;
    unsigned uv = lds32(scrR + (((r * 16 + cp) * SCRW + lane) << 2));
    __half2 h = *reinterpret_cast<__half2*>(&uv);
    int co = cp * 2;
    float v0 = fmaxf(__low2float(h)  + sbias[co],     0.f);
    float v1 = fmaxf(__high2float(h) + sbias[co + 1], 0.f);
    float* o = ob + (size_t)co * HW + ((pby + r) << 8) + pbx + lane;
    o[0]  = v0;
    o[HW] = v1;
}

__global__ __launch_bounds__(NT, 2)
void tbconv_defer_kernel(const float* __restrict__ x,
                         const float* __restrict__ gamma,
                         const float* __restrict__ beta,
                         const float* __restrict__ mean,
                         const float* __restrict__ var,
                         const float* __restrict__ w,
                         const float* __restrict__ bias,
                         float* __restrict__ out)
{
    extern __shared__ char smraw[];
    uint4* wfragsm = (uint4*)(smraw + OFF_WF);
    float* sinvf   = (float*)(smraw + OFF_SI);
    float* sshf    = (float*)(smraw + OFF_SS);
    float* sbias   = (float*)(smraw + OFF_SB);

    const int tid  = threadIdx.x;
    const int lane = tid & 31;
    const int wid  = tid >> 5;

    // ---- one-time setup ----
    if (tid < 32) {
        float inv = gamma[tid] * rsqrtf(var[tid] + 1e-4f);
        sinvf[tid] = inv;
        sshf[tid]  = beta[tid] - mean[tid] * inv;
        sbias[tid] = bias[tid];
    }
    // weights pre-shuffled into mma B-fragment order, nt-paired uint4:
    for (int i = tid; i < NWF4; i += NT) {
        int t = i & 31, np = (i >> 5) & 1, s = (i >> 6) & 1, tap = i >> 7;
        int ci = s * 16 + (t & 3) * 2;
        const float* wb0 = w + ((np * 16 + (t >> 2)) * 32 + ci) * 9 + tap;
        const float* wb1 = wb0 + 8 * 32 * 9;
        __half2 lo0 = __floats2half2_rn(wb0[0],  wb0[9]);
        __half2 hi0 = __floats2half2_rn(wb0[72], wb0[81]);
        __half2 lo1 = __floats2half2_rn(wb1[0],  wb1[9]);
        __half2 hi1 = __floats2half2_rn(wb1[72], wb1[81]);
        uint4 v;
        v.x = *(unsigned*)&lo0; v.y = *(unsigned*)&hi0;
        v.z = *(unsigned*)&lo1; v.w = *(unsigned*)&hi1;
        wfragsm[i] = v;
    }

    const unsigned smb = (unsigned)__cvta_generic_to_shared(smraw);
    const unsigned q0a = smb + OFF_Q0;
    const unsigned q1a = q0a + QTILE * 2;
    const unsigned scr0 = smb + OFF_SCR;
    const unsigned scr1 = scr0 + SCRBUF * 4;

    const int pxl0 = (lane & 7) + ((lane >> 3) & 1) * 8;
    const int cih  = (lane >> 4) * 8;
    const int m0   = lane >> 2;
    const int cb   = (lane & 3) * 2;

    int cur = blockIdx.x;
    int b  = cur >> 8;
    int by = ((cur >> 3) & 31) << 3;
    int bx = (cur & 7) << 5;

    __syncthreads();   // setup visible

    // BN constants in registers (used by builders)
    float ivr[8], shr[8];
    {
        int g8 = (wid & 3) * 8;
#pragma unroll
        for (int j = 0; j < 8; ++j) { ivr[j] = sinvf[g8 + j]; shr[j] = sshf[g8 + j]; }
    }

    // ---- prologue: ALL 8 warps build tile 0 into q0 ----
    {
        const float* xb = x + (size_t)b * C_CH * HW;
        int g = wid & 3;
        int rbase = (wid >> 2) * 5;
        float F[8];
#pragma unroll
        for (int k = 0; k < 5; ++k) {
            ldrow(xb, by, bx, rbase + k, g, lane, F);
            strow(q0a, by, rbase + k, g, lane, ivr, shr, F);
        }
        halo_item(q0a, xb, by, bx, tid, sinvf, sshf);
    }
    __syncthreads();

    bool flip = false;
    bool pvalid = false;
    int pb = 0, pby = 0, pbx = 0;

    while (cur < NTILES) {
        const unsigned qc   = flip ? q1a : q0a;
        const unsigned qn   = flip ? q0a : q1a;
        const unsigned scrW = flip ? scr1 : scr0;   // tile i scratch
        const unsigned scrR = flip ? scr0 : scr1;   // tile i-1 scratch

        const int nxt = cur + NCTA;
        const bool hasnext = (nxt < NTILES);
        int nb = 0, nby = 0, nbx = 0;
        if (hasnext) {
            nb  = nxt >> 8;
            nby = ((nxt >> 3) & 31) << 3;
            nbx = (nxt & 7) << 5;
        }

        if (wid < 4) {
            // ============ MMA role: 2 rows x 32 px x 32 co ============
            const int r0 = wid * 2;
            float acc[2][2][4][4];
#pragma unroll
            for (int rr = 0; rr < 2; ++rr)
#pragma unroll
                for (int mt = 0; mt < 2; ++mt)
#pragma unroll
                    for (int nt = 0; nt < 4; ++nt)
#pragma unroll
                        for (int k = 0; k < 4; ++k) acc[rr][mt][nt][k] = 0.f;

            // k-loop over (S, dx); A fragments dedup'd across dy
#pragma unroll
            for (int S = 0; S < 2; ++S) {
#pragma unroll
                for (int dx = 0; dx < 3; ++dx) {
                    uint4 wfa[3], wfb[3];
#pragma unroll
                    for (int dy = 0; dy < 3; ++dy) {
                        const int tap = dy * 3 + dx;
                        wfa[dy] = wfragsm[(((tap * 2 + S) * 2) + 0) * 32 + lane];
                        wfb[dy] = wfragsm[(((tap * 2 + S) * 2) + 1) * 32 + lane];
                    }
                    unsigned af[4][2][4];
#pragma unroll
                    for (int j = 0; j < 4; ++j) {
#pragma unroll
                        for (int mt = 0; mt < 2; ++mt) {
                            unsigned addr = qc +
                                ((((r0 + j) * QPX + mt * 16 + dx + pxl0) * CIP
                                  + cih + S * 16) << 1);
                            ldsm_x4(af[j][mt][0], af[j][mt][1],
                                    af[j][mt][2], af[j][mt][3], addr);
                        }
                    }
#pragma unroll
                    for (int dy = 0; dy < 3; ++dy) {
#pragma unroll
                        for (int rr = 0; rr < 2; ++rr) {
                            const int j = rr + dy;
#pragma unroll
                            for (int mt = 0; mt < 2; ++mt) {
                                const unsigned *a = af[j][mt];
                                mma16816(acc[rr][mt][0][0], acc[rr][mt][0][1],
                                         acc[rr][mt][0][2], acc[rr][mt][0][3],
                                         a[0], a[1], a[2], a[3],
                                         wfa[dy].x, wfa[dy].y);
                                mma16816(acc[rr][mt][1][0], acc[rr][mt][1][1],
                                         acc[rr][mt][1][2], acc[rr][mt][1][3],
                                         a[0], a[1], a[2], a[3],
                                         wfa[dy].z, wfa[dy].w);
                                mma16816(acc[rr][mt][2][0], acc[rr][mt][2][1],
                                         acc[rr][mt][2][2], acc[rr][mt][2][3],
                                         a[0], a[1], a[2], a[3],
                                         wfb[dy].x, wfb[dy].y);
                                mma16816(acc[rr][mt][3][0], acc[rr][mt][3][1],
                                         acc[rr][mt][3][2], acc[rr][mt][3][3],
                                         a[0], a[1], a[2], a[3],
                                         wfb[dy].z, wfb[dy].w);
                            }
                        }
                    }
                }
            }

            // ==== pack accs to fp16 scratch (STS only; drained next iter) ====
#pragma unroll
            for (int rr = 0; rr < 2; ++rr) {
                const int r = r0 + rr;
#pragma unroll
                for (int nt = 0; nt < 4; ++nt) {
                    const int cp = nt * 4 + (lane & 3);
#pragma unroll
                    for (int mt = 0; mt < 2; ++mt) {
                        const int px = m0 + mt * 16;
                        unsigned base = scrW + (((r * 16 + cp) * SCRW + px) << 2);
                        sts32(base,      h2bits(acc[rr][mt][nt][0], acc[rr][mt][nt][1]));
                        sts32(base + 32, h2bits(acc[rr][mt][nt][2], acc[rr][mt][nt][3]));
                    }
                }
            }
        } else {
            // ============ builder role ============
            if (hasnext) {
                const float* xbn = x + (size_t)nb * C_CH * HW;
                const int g = wid & 3;
                float FA[8], FB[8];
                ldrow(xbn, nby, nbx, 0, g, lane, FA);
#pragma unroll
                for (int r = 0; r < 10; r += 2) {
                    ldrow(xbn, nby, nbx, r + 1, g, lane, FB);
                    strow(qn, nby, r, g, lane, ivr, shr, FA);
                    if (r + 2 < 10) ldrow(xbn, nby, nbx, r + 2, g, lane, FA);
                    strow(qn, nby, r + 1, g, lane, ivr, shr, FB);
                }
                halo_item(qn, xbn, nby, nbx, g * 32 + lane, sinvf, sshf);
            }
            if (pvalid) {
                float* ob = out + (size_t)pb * C_CH * HW;
                const int bw = wid - 4;
#pragma unroll 8
                for (int j = 0; j < 32; ++j)
                    drain_unit(scrR, sbias, ob, pby, pbx, bw * 32 + j, lane);
            }
        }

        __syncthreads();
        pvalid = true; pb = b; pby = by; pbx = bx;
        cur = nxt; b = nb; by = nby; bx = nbx;
        flip = !flip;
    }

    // ---- final drain: last tile's scratch, all 8 warps ----
    if (pvalid) {
        const unsigned scrL = flip ? scr0 : scr1;   // last write buffer
        float* ob = out + (size_t)pb * C_CH * HW;
#pragma unroll 8
        for (int j = 0; j < 16; ++j)
            drain_unit(scrL, sbias, ob, pby, pbx, wid * 16 + j, lane);
    }
}

extern "C" void kernel_launch(void* const* d_in, const int* in_sizes, int n_in,
                              void* d_out, int out_size)
{
    const float* x     = (const float*)d_in[0];
    const float* gamma = (const float*)d_in[1];
    const float* beta  = (const float*)d_in[2];
    const float* mean  = (const float*)d_in[3];
    const float* var   = (const float*)d_in[4];
    const float* w     = (const float*)d_in[5];
    const float* bias  = (const float*)d_in[6];
    float* out = (float*)d_out;

    cudaFuncSetAttribute(tbconv_defer_kernel,
                         cudaFuncAttributeMaxDynamicSharedMemorySize, SMEM_BYTES);

    tbconv_defer_kernel<<<NCTA, NT, SMEM_BYTES>>>(x, gamma, beta, mean, var, w, bias, out);
}